// round 17
// baseline (speedup 1.0000x reference)
#include <cuda_runtime.h>

// 0: x [2,192,88,133] f32, 1: W_lin [133,24], 2: b_lin [24], 3: W_qkv [24,72],
// 4: b_qkv [72], 5: rpb [4,49,49], 6: W_proj [24,24], 7: b_proj [24]
// output: [2,192,88,24] f32

#define BB   2
#define HT   192
#define WD   88
#define FIN  133
#define CC   24
#define NH   4
#define DH   6
#define WIN  25
#define NPIX (BB*HT*WD)   // 33792
#define NBI  (BB*HT)      // 384
#define RPBW 49
#define TR   3            // query rows per attn block
#define NT   352          // attn threads: 88 cols x 4 heads
#define BROWS 29
#define BH   (BROWS*RPBW) // 1421
#define LOG2E 1.4426950408889634f
#define NQ   44           // quads per (bi,ch)
#define KVTQ (CC*NQ)      // 1056 quads per row tile
#define BIAS2_ULL 5688    // 1 front pad + 5684 pairs + back pads (even)
#define SMEM_BYTES (BIAS2_ULL*8 + 4*KVTQ*16) // 45504 + 67584 = 113088

typedef unsigned long long ull;

// Scratch (device globals: allocation-free). KV in quad-interleaved float4
// layout [bi][ch][44]{k0,k1,v0,v1} -> 16B-aligned LDG/STS/LDS.128.
__device__ float  g_q  [NPIX*CC];            // [bi][ch][col]
__device__ float  g_q2 [NPIX*CC];
__device__ float4 g_kv4 [NBI*CC*NQ];
__device__ float4 g_kv24[NBI*CC*NQ];
__device__ float  g_wc[CC*72], g_bc[72];

// ---- packed f32x2 helpers --------------------------------------------------
__device__ __forceinline__ ull pk2(float lo, float hi) {
    ull r; asm("mov.b64 %0, {%1,%2};" : "=l"(r) : "f"(lo), "f"(hi)); return r;
}
__device__ __forceinline__ ull bc2(float v) { return pk2(v, v); }
__device__ __forceinline__ void upk2(float& lo, float& hi, ull v) {
    asm("mov.b64 {%0,%1}, %2;" : "=f"(lo), "=f"(hi) : "l"(v));
}
__device__ __forceinline__ ull fma2(ull a, ull b, ull c) {
    ull d; asm("fma.rn.f32x2 %0, %1, %2, %3;" : "=l"(d) : "l"(a), "l"(b), "l"(c)); return d;
}
__device__ __forceinline__ ull add2(ull a, ull b) {
    ull d; asm("add.rn.f32x2 %0, %1, %2;" : "=l"(d) : "l"(a), "l"(b)); return d;
}
__device__ __forceinline__ ull mul2(ull a, ull b) {
    ull d; asm("mul.rn.f32x2 %0, %1, %2;" : "=l"(d) : "l"(a), "l"(b)); return d;
}
__device__ __forceinline__ float ex2f(float x) {
    float y; asm("ex2.approx.f32 %0, %1;" : "=f"(y) : "f"(x)); return y;
}
__device__ __forceinline__ ull lds64(const float* p) {
    return *reinterpret_cast<const ull*>(p);   // even float offset from 16B base
}

// ---------------------------------------------------------------------------
// Setup: Wcomb = W_proj @ W_qkv, bcomb = b_proj @ W_qkv + b_qkv
// (q columns scaled by dh^-0.5 * log2(e) for raw ex2 in attention)
// ---------------------------------------------------------------------------
__global__ void k_comb(const float* __restrict__ Wp, const float* __restrict__ bp,
                       const float* __restrict__ Wq, const float* __restrict__ bq) {
    int t = blockIdx.x * blockDim.x + threadIdx.x;
    const float QS = 0.40824829046386302f * LOG2E;
    if (t < CC*72) {
        int u = t / 72, cf = t % 72;
        float a = 0.f;
        #pragma unroll
        for (int w = 0; w < CC; ++w) a = fmaf(Wp[u*CC + w], Wq[w*72 + cf], a);
        if (cf < CC) a *= QS;
        g_wc[t] = a;
    }
    if (t < 72) {
        float a = bq[t];
        #pragma unroll
        for (int w = 0; w < CC; ++w) a = fmaf(bp[w], Wq[w*72 + t], a);
        if (t < CC) a *= QS;
        g_bc[t] = a;
    }
}

// ---------------------------------------------------------------------------
// Fused linear+ReLU+qkv, f32x2-packed: block = 44-pixel half row.
// ---------------------------------------------------------------------------
#define XS_STR 134
#define WL_STR 134
#define HS_STR 26
#define WQ_STR 26

__global__ void __launch_bounds__(352) k_linqkv(const float* __restrict__ x,
                                                const float* __restrict__ Wl,
                                                const float* __restrict__ bl,
                                                const float* __restrict__ Wq,
                                                const float* __restrict__ bq) {
    __shared__ __align__(16) float sm[12128];
    float* xs  = sm;                       // 44*134 = 5896
    float* wlT = sm + 5896;                // 24*134 = 3216 (wlT[c][f])
    float* hs  = sm + 9112;                // 44*26  = 1144
    float* wqT = sm + 10256;               // 72*26  = 1872 (wqT[cf][u])

    int blk = blockIdx.x;
    int bi = blk >> 1, jb = (blk & 1) * 44;
    int tid = threadIdx.x;

    const float* xb = x + ((size_t)bi * WD + jb) * FIN;
    for (int idx = tid; idx < 44*FIN; idx += 352)
        xs[(idx / FIN) * XS_STR + (idx % FIN)] = xb[idx];
    for (int idx = tid; idx < FIN*CC; idx += 352)
        wlT[(idx % CC) * WL_STR + (idx / CC)] = Wl[idx];
    for (int idx = tid; idx < CC*72; idx += 352)
        wqT[(idx % 72) * WQ_STR + (idx / 72)] = Wq[idx];
    __syncthreads();

    int jl = tid % 44, cg = tid / 44;
    int c0 = cg * 3;
    ull acc2[3];
    float accs[3];
    #pragma unroll
    for (int i = 0; i < 3; ++i) { acc2[i] = 0ULL; accs[i] = bl[c0 + i]; }

    const float* xrow = xs + jl * XS_STR;
    #pragma unroll 6
    for (int fp = 0; fp < 66; ++fp) {
        ull xp = lds64(xrow + 2*fp);
        #pragma unroll
        for (int i = 0; i < 3; ++i)
            acc2[i] = fma2(xp, lds64(wlT + (c0 + i)*WL_STR + 2*fp), acc2[i]);
    }
    {
        float xf = xrow[132];
        #pragma unroll
        for (int i = 0; i < 3; ++i)
            accs[i] = fmaf(xf, wlT[(c0 + i)*WL_STR + 132], accs[i]);
    }
    #pragma unroll
    for (int i = 0; i < 3; ++i) {
        float lo, hi; upk2(lo, hi, acc2[i]);
        hs[jl*HS_STR + c0 + i] = fmaxf(lo + hi + accs[i], 0.f);
    }
    __syncthreads();

    const float QS = 0.40824829046386302f * LOG2E;
    float* kvf = reinterpret_cast<float*>(g_kv4);
    for (int o = tid; o < 44*72; o += 352) {
        int cf = o / 44, j2 = o - cf*44;
        ull a2 = 0ULL;
        const float* hrow = hs + j2 * HS_STR;
        const float* wrow = wqT + cf * WQ_STR;
        #pragma unroll
        for (int up = 0; up < 12; ++up)
            a2 = fma2(lds64(hrow + 2*up), lds64(wrow + 2*up), a2);
        float lo, hi; upk2(lo, hi, a2);
        float a = lo + hi + bq[cf];
        int which = cf / CC, ch = cf % CC;
        int j = jb + j2;
        if (which == 0) {
            g_q[((size_t)bi * CC + ch) * WD + j] = a * QS;
        } else {
            kvf[(((size_t)bi * CC + ch) * NQ + (j >> 1)) * 4 + (j & 1)
                + (which == 2 ? 2 : 0)] = a;
        }
    }
}

// ---------------------------------------------------------------------------
// Attention (TR=3, 352 thr, grid 128): TWO key rows per barrier. Pair of
// rows staged into a double-buffered pair tile (one __syncthreads per PAIR),
// inner loop interleaves row-A and row-B score chains -> 6 independent
// dependency chains per warp. Packed bias pairs (LDS.64), LDS.128 K/V,
// log2-domain scores, raw ex2. Odd tail row duplicated with -87 kill.
// MODE 0: epilogue -> layer-2 q/kv via Wcomb. MODE 1: final projection.
// ---------------------------------------------------------------------------
template<int MODE>
__global__ void __launch_bounds__(NT, 1) k_attn(
    const float* __restrict__ Q, const float4* __restrict__ KV,
    const float* __restrict__ rpb,
    const float* __restrict__ W, const float* __restrict__ bvec,
    float* __restrict__ outp)
{
    extern __shared__ float smem[];          // dynamic, 16B aligned
    ull* bias2 = reinterpret_cast<ull*>(smem) + 1;   // +1: front pad (cb=-1)

    int blk = blockIdx.x;           // 128 blocks
    int b = blk >> 6, it = blk & 63;
    int i0 = it * TR;
    int tid = threadIdx.x;
    int j = tid % WD, h = tid / WD, h6 = h * DH;

    int sii[TR];
    #pragma unroll
    for (int t = 0; t < TR; ++t) sii[t] = min(max(i0 + t - 12, 0), HT - WIN);
    int r_lo = sii[0];
    int nrows = sii[2] + WIN - r_lo;           // 25..27
    int row_base = r_lo - i0 + 22;

    int sjj = min(max(j - 12, 0), WD - WIN);
    int e0 = sjj & 1;
    int c0 = sjj - e0;                          // even-aligned window start
    int qb0 = c0 >> 1;                          // quad base [0,31]
    int cb = c0 + 24 - j;                       // bias column base (>= -1)

    // Stage overlapping packed bias pairs: bias2[hh][rr][c] = {b[c], b[c+1]}
    if (tid == 0) reinterpret_cast<ull*>(smem)[0] = 0ULL;   // front pad
    for (int idx = tid; idx < NH*BH; idx += NT) {
        int hh = idx / BH, rem = idx - hh*BH;
        int rr = rem / RPBW, c = rem - rr*RPBW;
        int src = min(max(row_base + rr, 0), RPBW - 1);
        const float* rp = rpb + hh*RPBW*RPBW + src*RPBW;
        float lo = rp[c] * LOG2E;
        float hi = (c < RPBW - 1) ? rp[c + 1] * LOG2E : 0.f;
        bias2[idx] = pk2(lo, hi);
    }
    if (tid < 3) bias2[NH*BH + tid] = 0ULL;    // back pads (masked edge reads)

    // q vectors (broadcast-packed) + negated center scores (log2 units)
    float nsc[TR];
    ull qv2[TR][DH];
    const float* KVf = reinterpret_cast<const float*>(KV);
    #pragma unroll
    for (int t = 0; t < TR; ++t) {
        const float* qp = Q + ((size_t)(b*HT + i0 + t) * CC + h6) * WD + j;
        size_t kcq = (((size_t)(b*HT + i0 + t) * CC + h6) * NQ + (j >> 1)) * 4 + (j & 1);
        float s = 0.f;
        #pragma unroll
        for (int d = 0; d < DH; ++d) {
            float qd = qp[d*WD];
            s = fmaf(qd, KVf[kcq + (size_t)d*NQ*4], s);
            qv2[t][d] = bc2(qd);
        }
        nsc[t] = -s;
    }

    // edge masks (thread-constant)
    ull mfirst = pk2(e0 ? 0.f : 1.f, 1.f);
    ull mlast  = pk2(1.f, e0 ? 1.f : 0.f);

    ull accp[TR][DH], lp[TR];
    #pragma unroll
    for (int t = 0; t < TR; ++t) {
        lp[t] = 0ULL;
        #pragma unroll
        for (int d = 0; d < DH; ++d) accp[t][d] = 0ULL;
    }

    float4* sbuf = reinterpret_cast<float4*>(smem + BIAS2_ULL*2);
    int npairs = (nrows + 1) >> 1;             // 13 or 14

    // prefetch first pair (rows 0,1) — 6 quads per thread
    float4 kvr[6];
    {
        const float4* srcA = KV + (size_t)(b*HT + r_lo) * CC * NQ;
        const float4* srcB = KV + (size_t)(b*HT + r_lo + 1) * CC * NQ;
        #pragma unroll
        for (int u = 0; u < 3; ++u) {
            kvr[u]     = srcA[tid + u*NT];
            kvr[u + 3] = srcB[tid + u*NT];
        }
    }

    for (int m = 0; m < npairs; ++m) {
        float4* bufA = sbuf + (m & 1) * (2*KVTQ);
        float4* bufB = bufA + KVTQ;
        #pragma unroll
        for (int u = 0; u < 3; ++u) {
            bufA[tid + u*NT] = kvr[u];
            bufB[tid + u*NT] = kvr[u + 3];
        }
        __syncthreads();                      // ONE barrier per pair

        int ra2 = 2*(m + 1);
        if (ra2 < nrows) {                    // prefetch next pair
            int rb2 = min(ra2 + 1, nrows - 1);
            const float4* srcA = KV + (size_t)(b*HT + r_lo + ra2) * CC * NQ;
            const float4* srcB = KV + (size_t)(b*HT + r_lo + rb2) * CC * NQ;
            #pragma unroll
            for (int u = 0; u < 3; ++u) {
                kvr[u]     = srcA[tid + u*NT];
                kvr[u + 3] = srcB[tid + u*NT];
            }
        }

        int rrA = 2*m, rrB = min(2*m + 1, nrows - 1);
        int rA = r_lo + rrA, rB = r_lo + rrB;
        float dup = (2*m + 1 < nrows) ? 0.f : -87.f;   // kill duplicated tail

        ull shpA[TR], shpB[TR];
        shpA[0] = bc2(nsc[0] + ((rA <= sii[0] + 24) ? 0.f : -87.f));
        shpA[1] = bc2(nsc[1] + ((rA >= sii[1] && rA <= sii[1] + 24) ? 0.f : -87.f));
        shpA[2] = bc2(nsc[2] + ((rA >= sii[2]) ? 0.f : -87.f));
        shpB[0] = bc2(nsc[0] + ((rB <= sii[0] + 24) ? 0.f : -87.f) + dup);
        shpB[1] = bc2(nsc[1] + ((rB >= sii[1] && rB <= sii[1] + 24) ? 0.f : -87.f) + dup);
        shpB[2] = bc2(nsc[2] + ((rB >= sii[2]) ? 0.f : -87.f) + dup);

        const ulonglong2* kvpA = reinterpret_cast<const ulonglong2*>(bufA) + h6*NQ + qb0;
        const ulonglong2* kvpB = reinterpret_cast<const ulonglong2*>(bufB) + h6*NQ + qb0;
        const ull* bbA = bias2 + h*BH + (rrA + 2)*RPBW + cb;   // query t: bbA - t*RPBW
        const ull* bbB = bias2 + h*BH + (rrB + 2)*RPBW + cb;

        #pragma unroll
        for (int p = 0; p < 13; ++p) {
            // row A
            {
                ull kpair[DH], vpair[DH];
                #pragma unroll
                for (int d = 0; d < DH; ++d) {
                    ulonglong2 u2 = kvpA[d*NQ + p];
                    kpair[d] = u2.x; vpair[d] = u2.y;
                }
                #pragma unroll
                for (int t = 0; t < TR; ++t) {
                    ull sA = add2(bbA[2*p - t*RPBW], shpA[t]);
                    #pragma unroll
                    for (int d = 0; d < 3; ++d) sA = fma2(qv2[t][d], kpair[d], sA);
                    ull sB2 = mul2(qv2[t][3], kpair[3]);
                    sB2 = fma2(qv2[t][4], kpair[4], sB2);
                    sB2 = fma2(qv2[t][5], kpair[5], sB2);
                    float s0, s1; upk2(s0, s1, add2(sA, sB2));
                    ull pp = pk2(ex2f(s0), ex2f(s1));
                    if (p == 0)  pp = mul2(pp, mfirst);
                    if (p == 12) pp = mul2(pp, mlast);
                    lp[t] = add2(lp[t], pp);
                    #pragma unroll
                    for (int d = 0; d < DH; ++d) accp[t][d] = fma2(pp, vpair[d], accp[t][d]);
                }
            }
            // row B (independent chains -> overlaps row A's latency)
            {
                ull kpair[DH], vpair[DH];
                #pragma unroll
                for (int d = 0; d < DH; ++d) {
                    ulonglong2 u2 = kvpB[d*NQ + p];
                    kpair[d] = u2.x; vpair[d] = u2.y;
                }
                #pragma unroll
                for (int t = 0; t < TR; ++t) {
                    ull sA = add2(bbB[2*p - t*RPBW], shpB[t]);
                    #pragma unroll
                    for (int d = 0; d < 3; ++d) sA = fma2(qv2[t][d], kpair[d], sA);
                    ull sB2 = mul2(qv2[t][3], kpair[3]);
                    sB2 = fma2(qv2[t][4], kpair[4], sB2);
                    sB2 = fma2(qv2[t][5], kpair[5], sB2);
                    float s0, s1; upk2(s0, s1, add2(sA, sB2));
                    ull pp = pk2(ex2f(s0), ex2f(s1));
                    if (p == 0)  pp = mul2(pp, mfirst);
                    if (p == 12) pp = mul2(pp, mlast);
                    lp[t] = add2(lp[t], pp);
                    #pragma unroll
                    for (int d = 0; d < DH; ++d) accp[t][d] = fma2(pp, vpair[d], accp[t][d]);
                }
            }
        }
    }

    // ---- epilogue (f32x2-packed GEMMs; reuses smem as float region) --------
    __syncthreads();
    float* attn_s = smem;                    // [3][88][25] = 6600
    const int NOUT = (MODE == 0) ? 72 : 24;
    float* ws = smem + 6600;                 // <=1728 (even offset)
    float* bs = smem + 8328;                 // <=72   (even offset)
    #pragma unroll
    for (int t = 0; t < TR; ++t) {
        float l0, l1; upk2(l0, l1, lp[t]);
        float inv = __fdividef(1.f, l0 + l1);
        #pragma unroll
        for (int d = 0; d < DH; ++d) {
            float a0, a1; upk2(a0, a1, accp[t][d]);
            attn_s[(t*WD + j)*25 + h6 + d] = (a0 + a1) * inv;
        }
    }
    for (int idx = tid; idx < CC*NOUT; idx += NT) ws[idx] = W[idx];
    for (int idx = tid; idx < NOUT; idx += NT) bs[idx] = bvec[idx];
    __syncthreads();

    if (MODE == 0) {
        float* kvo = reinterpret_cast<float*>(g_kv24);
        #pragma unroll
        for (int pass = 0; pass < 3; ++pass) {
            int cf0 = h * 18 + pass * 6;      // even; never straddles q/k/v
            ull a2[TR][3];
            #pragma unroll
            for (int t = 0; t < TR; ++t)
                #pragma unroll
                for (int cp = 0; cp < 3; ++cp) a2[t][cp] = lds64(bs + cf0 + 2*cp);
            #pragma unroll
            for (int u = 0; u < CC; ++u) {
                ull wvp[3];
                #pragma unroll
                for (int cp = 0; cp < 3; ++cp) wvp[cp] = lds64(ws + u*72 + cf0 + 2*cp);
                #pragma unroll
                for (int t = 0; t < TR; ++t) {
                    ull avb = bc2(attn_s[(t*WD + j)*25 + u]);
                    #pragma unroll
                    for (int cp = 0; cp < 3; ++cp) a2[t][cp] = fma2(avb, wvp[cp], a2[t][cp]);
                }
            }
            int which = (cf0 >= 48) ? 2 : (cf0 >= 24 ? 1 : 0);
            int chb = cf0 - which * CC;
            int voff = (which == 2) ? 2 : 0;
            #pragma unroll
            for (int t = 0; t < TR; ++t) {
                size_t bi_t = (size_t)(b*HT + i0 + t);
                #pragma unroll
                for (int cp = 0; cp < 3; ++cp) {
                    float lo, hi; upk2(lo, hi, a2[t][cp]);
                    int ci = chb + 2*cp;
                    if (which == 0) {
                        g_q2[(bi_t * CC + ci) * WD + j]     = lo;
                        g_q2[(bi_t * CC + ci + 1) * WD + j] = hi;
                    } else {
                        kvo[((bi_t * CC + ci) * NQ + (j >> 1)) * 4 + (j & 1) + voff]     = lo;
                        kvo[((bi_t * CC + ci + 1) * NQ + (j >> 1)) * 4 + (j & 1) + voff] = hi;
                    }
                }
            }
        }
    } else {
        int cf0 = h * 6;                     // even
        ull a2[TR][3];
        #pragma unroll
        for (int t = 0; t < TR; ++t)
            #pragma unroll
            for (int cp = 0; cp < 3; ++cp) a2[t][cp] = lds64(bs + cf0 + 2*cp);
        #pragma unroll
        for (int u = 0; u < CC; ++u) {
            ull wvp[3];
            #pragma unroll
            for (int cp = 0; cp < 3; ++cp) wvp[cp] = lds64(ws + u*24 + cf0 + 2*cp);
            #pragma unroll
            for (int t = 0; t < TR; ++t) {
                ull avb = bc2(attn_s[(t*WD + j)*25 + u]);
                #pragma unroll
                for (int cp = 0; cp < 3; ++cp) a2[t][cp] = fma2(avb, wvp[cp], a2[t][cp]);
            }
        }
        __syncthreads();
        float* res_s = smem;                 // [3][88][24] = 6336
        #pragma unroll
        for (int t = 0; t < TR; ++t)
            #pragma unroll
            for (int cp = 0; cp < 3; ++cp) {
                float lo, hi; upk2(lo, hi, a2[t][cp]);
                res_s[(t*WD + j)*CC + cf0 + 2*cp]     = lo;
                res_s[(t*WD + j)*CC + cf0 + 2*cp + 1] = hi;
            }
        __syncthreads();
        float* ob = outp + (size_t)(b*HT + i0) * WD * CC;
        for (int o = tid; o < TR*WD*CC; o += NT) ob[o] = res_s[o];
    }
}

// ---------------------------------------------------------------------------
extern "C" void kernel_launch(void* const* d_in, const int* in_sizes, int n_in,
                              void* d_out, int out_size) {
    (void)in_sizes; (void)n_in; (void)out_size;
    const float* x      = (const float*)d_in[0];
    const float* W_lin  = (const float*)d_in[1];
    const float* b_lin  = (const float*)d_in[2];
    const float* W_qkv  = (const float*)d_in[3];
    const float* b_qkv  = (const float*)d_in[4];
    const float* rpb    = (const float*)d_in[5];
    const float* W_proj = (const float*)d_in[6];
    const float* b_proj = (const float*)d_in[7];
    float* out = (float*)d_out;

    float *q, *q2, *wc, *bc;
    float4 *kv, *kv2;
    cudaGetSymbolAddress((void**)&q,   g_q);
    cudaGetSymbolAddress((void**)&q2,  g_q2);
    cudaGetSymbolAddress((void**)&kv,  g_kv4);
    cudaGetSymbolAddress((void**)&kv2, g_kv24);
    cudaGetSymbolAddress((void**)&wc,  g_wc);
    cudaGetSymbolAddress((void**)&bc,  g_bc);

    cudaFuncSetAttribute(k_attn<0>, cudaFuncAttributeMaxDynamicSharedMemorySize, SMEM_BYTES);
    cudaFuncSetAttribute(k_attn<1>, cudaFuncAttributeMaxDynamicSharedMemorySize, SMEM_BYTES);

    k_comb<<<7, 256>>>(W_proj, b_proj, W_qkv, b_qkv);
    k_linqkv<<<BB*HT*2, 352>>>(x, W_lin, b_lin, W_qkv, b_qkv);
    k_attn<0><<<128, NT, SMEM_BYTES>>>(q,  kv,  rpb, wc,     bc,     nullptr);
    k_attn<1><<<128, NT, SMEM_BYTES>>>(q2, kv2, rpb, W_proj, b_proj, out);
}